// round 12
// baseline (speedup 1.0000x reference)
#include <cuda_runtime.h>
#include <math.h>
#include <cstdint>

#define EPSF 1e-5f

// Problem constants
#define BATCH 32
#define CIN   512
#define COUT  512
#define HW    3136   // 56*56
#define KNUM  4
#define ADIM  32

#define NMT  (COUT / 16)   // 32 m-tiles
#define NKT8 (CIN / 8)     // 64 k8-tiles
#define NTP  (HW / 16)     // 196 n-tile-pairs

// GEMM tiling (direct-from-global, no smem)
#define BM 128
#define BN 128

// prepack smem: 8 rows x (3136 + 8 pad) floats
#define PRE_SROW 3144
#define PREPACK_SMEM_BYTES (8 * PRE_SROW * 4)   // 100608 B

// ---------------- device scratch ----------------
__device__ float g_pooled[BATCH * CIN];
__device__ float g_ch[BATCH * CIN];
__device__ float g_rowscale[BATCH * COUT];
__device__ float g_kn[BATCH * KNUM];
__device__ float g_bias[COUT];
__device__ float g_weff[BATCH * NMT * NKT8 * 32 * 4];
__device__ float g_xpack[(size_t)BATCH * NKT8 * NTP * 32 * 4];

// ================= helpers =================
__device__ __forceinline__ float cvt_tf32(float v) {
    uint32_t u;
    asm("cvt.rna.tf32.f32 %0, %1;" : "=r"(u) : "f"(v));
    return __uint_as_float(u);
}

__device__ __forceinline__ void mma16n8k8(float (&d)[4], const uint32_t a0, const uint32_t a1,
                                          const uint32_t a2, const uint32_t a3,
                                          const uint32_t b0, const uint32_t b1) {
    asm volatile(
        "mma.sync.aligned.m16n8k8.row.col.f32.tf32.tf32.f32 "
        "{%0,%1,%2,%3}, {%4,%5,%6,%7}, {%8,%9}, {%0,%1,%2,%3};"
        : "+f"(d[0]), "+f"(d[1]), "+f"(d[2]), "+f"(d[3])
        : "r"(a0), "r"(a1), "r"(a2), "r"(a3), "r"(b0), "r"(b1));
}

__device__ __forceinline__ float warp_sum(float v) {
    #pragma unroll
    for (int off = 16; off > 0; off >>= 1)
        v += __shfl_xor_sync(0xffffffffu, v, off);
    return v;
}

// ---------------- Kernel A: prepack x -> tf32 B-fragments, single sync -----
__global__ __launch_bounds__(256)
void prepack_kernel(const float* __restrict__ x) {
    extern __shared__ float sx[];   // [8][PRE_SROW]

    const int bx  = blockIdx.x;
    const int b   = bx >> 6;
    const int kt8 = bx & 63;
    const int tid = threadIdx.x;
    const int lane = tid & 31;
    const int w    = tid >> 5;

    const float4* Xr = reinterpret_cast<const float4*>(
        x + ((size_t)b * CIN + kt8 * 8 + w) * HW);
    float4* Op = reinterpret_cast<float4*>(g_xpack) +
                 ((size_t)(b * NKT8 + kt8) * NTP) * 32;

    float psum = 0.f;
    float* srow = sx + w * PRE_SROW;
    for (int i = lane; i < HW / 4; i += 32) {
        float4 v = Xr[i];
        psum += v.x + v.y + v.z + v.w;
        *reinterpret_cast<float4*>(&srow[i * 4]) = v;
    }
    psum = warp_sum(psum);
    if (lane == 0) g_pooled[b * CIN + kt8 * 8 + w] = psum * (1.0f / HW);

    __syncthreads();

    const int tg  = lane & 3;
    const int gid = lane >> 2;
    const float* r0 = sx + tg * PRE_SROW;
    const float* r1 = sx + (tg + 4) * PRE_SROW;
    #pragma unroll 5
    for (int r = 0; r < (NTP * 32 + 255) / 256; r++) {
        const int f = tid + 256 * r;
        const int ntpl = f >> 5;
        if (ntpl < NTP) {
            const int col0 = ntpl * 16 + gid;
            float4 o;
            o.x = cvt_tf32(r0[col0]);
            o.y = cvt_tf32(r1[col0]);
            o.z = cvt_tf32(r0[col0 + 8]);
            o.w = cvt_tf32(r1[col0 + 8]);
            Op[(size_t)ntpl * 32 + lane] = o;
        }
    }
}

// ---------------- Kernel B: attention heads (grid 32x2) ----------
__global__ __launch_bounds__(256)
void attn_kernel(const float* __restrict__ fc_w,
                 const float* __restrict__ abn_g, const float* __restrict__ abn_b,
                 const float* __restrict__ abn_m, const float* __restrict__ abn_v,
                 const float* __restrict__ ch_w, const float* __restrict__ ch_b,
                 const float* __restrict__ fl_w, const float* __restrict__ fl_b,
                 const float* __restrict__ kn_w, const float* __restrict__ kn_b,
                 const float* __restrict__ bn_g, const float* __restrict__ bn_b,
                 const float* __restrict__ bn_m, const float* __restrict__ bn_v) {
    __shared__ float sp[CIN];
    __shared__ float sh[ADIM];
    __shared__ float slog[KNUM];

    const int b = blockIdx.x;
    const int half = blockIdx.y;
    const int tid = threadIdx.x;
    const int wid = tid >> 5;
    const int lane = tid & 31;

    #pragma unroll
    for (int i = 0; i < CIN / 256; i++)
        sp[tid + 256 * i] = g_pooled[b * CIN + tid + 256 * i];
    __syncthreads();

    #pragma unroll
    for (int i = 0; i < 4; i++) {
        const int a = wid + 8 * i;
        const float* fr = &fc_w[a * CIN];
        float s = 0.f;
        #pragma unroll
        for (int c = 0; c < CIN / 32; c++)
            s += sp[lane + 32 * c] * fr[lane + 32 * c];
        s = warp_sum(s);
        if (lane == 0) {
            float inv_a = abn_g[a] * rsqrtf(abn_v[a] + EPSF);
            s = (s - abn_m[a]) * inv_a + abn_b[a];
            sh[a] = fmaxf(s, 0.f);
        }
    }
    __syncthreads();

    const float hv = sh[lane];

    if (half == 0) {
        for (int i = 0; i < 64; i++) {
            const int c = wid * 64 + i;
            float s = warp_sum(hv * ch_w[c * ADIM + lane]);
            if (lane == 0)
                g_ch[b * CIN + c] = 1.0f / (1.0f + __expf(-(s + ch_b[c])));
        }
    } else {
        for (int i = 0; i < 64; i++) {
            const int o = wid * 64 + i;
            float s = warp_sum(hv * fl_w[o * ADIM + lane]);
            if (lane == 0) {
                float fl = 1.0f / (1.0f + __expf(-(s + fl_b[o])));
                g_rowscale[b * COUT + o] = fl * bn_g[o] * rsqrtf(bn_v[o] + EPSF);
            }
        }
        if (wid == 0) {
            #pragma unroll
            for (int kk = 0; kk < KNUM; kk++) {
                float s = warp_sum(hv * kn_w[kk * ADIM + lane]);
                if (lane == 0) slog[kk] = s + kn_b[kk];
            }
            __syncwarp();
            if (lane == 0) {
                float m = fmaxf(fmaxf(slog[0], slog[1]), fmaxf(slog[2], slog[3]));
                float e0 = __expf(slog[0] - m), e1 = __expf(slog[1] - m);
                float e2 = __expf(slog[2] - m), e3 = __expf(slog[3] - m);
                float d = 1.0f / (e0 + e1 + e2 + e3);
                g_kn[b * KNUM + 0] = e0 * d;
                g_kn[b * KNUM + 1] = e1 * d;
                g_kn[b * KNUM + 2] = e2 * d;
                g_kn[b * KNUM + 3] = e3 * d;
            }
        }
        if (b == 0) {
            #pragma unroll
            for (int i = 0; i < COUT / 256; i++) {
                int o = tid + 256 * i;
                float inv = bn_g[o] * rsqrtf(bn_v[o] + EPSF);
                g_bias[o] = bn_b[o] - bn_m[o] * inv;
            }
        }
    }
}

// ---------------- Kernel C: effective weight, 4-way batch-split ----------------
__global__ __launch_bounds__(256)
void weff_kernel(const float* __restrict__ weight) {
    const int gidx = blockIdx.x * 256 + threadIdx.x;
    const int lane = gidx & 31;
    const int kt8 = (gidx >> 5) & (NKT8 - 1);
    const int mt  = (gidx >> 11) & (NMT - 1);
    const int bq  = gidx >> 16;            // 0..3

    const int gid = lane >> 2;
    const int tg  = lane & 3;
    const int o  = mt * 16 + gid;
    const int k  = kt8 * 8 + tg;

    float w[4][4];
    #pragma unroll
    for (int j = 0; j < KNUM; j++) {
        const float* wj = weight + ((size_t)j * COUT) * CIN;
        w[j][0] = wj[(size_t)o * CIN + k];
        w[j][1] = wj[(size_t)(o + 8) * CIN + k];
        w[j][2] = wj[(size_t)o * CIN + k + 4];
        w[j][3] = wj[(size_t)(o + 8) * CIN + k + 4];
    }

    float4* out = reinterpret_cast<float4*>(g_weff);
    const int b0 = bq * 8;
    #pragma unroll
    for (int bb = 0; bb < 8; bb++) {
        const int b = b0 + bb;
        const float kn0 = g_kn[b * KNUM + 0], kn1 = g_kn[b * KNUM + 1];
        const float kn2 = g_kn[b * KNUM + 2], kn3 = g_kn[b * KNUM + 3];
        const float rs0 = g_rowscale[b * COUT + o];
        const float rs1 = g_rowscale[b * COUT + o + 8];
        const float ch0 = g_ch[b * CIN + k];
        const float ch1 = g_ch[b * CIN + k + 4];

        float4 v;
        v.x = cvt_tf32(rs0 * ch0 * (kn0 * w[0][0] + kn1 * w[1][0] + kn2 * w[2][0] + kn3 * w[3][0]));
        v.y = cvt_tf32(rs1 * ch0 * (kn0 * w[0][1] + kn1 * w[1][1] + kn2 * w[2][1] + kn3 * w[3][1]));
        v.z = cvt_tf32(rs0 * ch1 * (kn0 * w[0][2] + kn1 * w[1][2] + kn2 * w[2][2] + kn3 * w[3][2]));
        v.w = cvt_tf32(rs1 * ch1 * (kn0 * w[0][3] + kn1 * w[1][3] + kn2 * w[2][3] + kn3 * w[3][3]));
        out[((size_t)(b * NMT + mt) * NKT8 + kt8) * 32 + lane] = v;
    }
}

// ---------------- Kernel D: barrier-free direct-global fragment GEMM ----
// Each warp streams its own A/B fragments from gmem (fragment-packed layouts).
// No smem, no __syncthreads in the mainloop.
__global__ __launch_bounds__(256, 2)
void gemm_mma_kernel(float* __restrict__ y) {
    const int tid  = threadIdx.x;
    const int lane = tid & 31;
    const int wid  = tid >> 5;
    const int wm   = wid >> 2;       // 0..1
    const int wn   = wid & 3;        // 0..3
    const int gid  = lane >> 2;
    const int tg   = lane & 3;

    const int mt0 = blockIdx.x * (BM / 16);
    const int o0  = blockIdx.x * BM;
    const int hw0 = blockIdx.y * BN;
    const int ntp0 = blockIdx.y * (BN / 16);
    const int b   = blockIdx.z;

    // A fragment pointers: [b][mt][kt8][lane]; advance 32 float4 per kt8
    const float4* pA[4];
    #pragma unroll
    for (int mi = 0; mi < 4; mi++) {
        const int mt = mt0 + wm * 4 + mi;
        pA[mi] = reinterpret_cast<const float4*>(g_weff) +
                 ((size_t)(b * NMT + mt) * NKT8) * 32 + lane;
    }
    // B fragment pointers: [b][kt8][ntp][lane]; advance NTP*32 float4 per kt8
    const float4* pB[2];
    #pragma unroll
    for (int p = 0; p < 2; p++) {
        int ntp = ntp0 + wn * 2 + p;
        if (ntp > NTP - 1) ntp = NTP - 1;   // clamp; results unused (col>=HW)
        pB[p] = reinterpret_cast<const float4*>(g_xpack) +
                ((size_t)(b * NKT8) * NTP + ntp) * 32 + lane;
    }

    float acc[4][4][4];
    #pragma unroll
    for (int mi = 0; mi < 4; mi++)
        #pragma unroll
        for (int ni = 0; ni < 4; ni++)
            #pragma unroll
            for (int r = 0; r < 4; r++) acc[mi][ni][r] = 0.f;

    #pragma unroll 4
    for (int kt8 = 0; kt8 < NKT8; kt8++) {
        float4 af[4];
        #pragma unroll
        for (int mi = 0; mi < 4; mi++) {
            af[mi] = *pA[mi];
            pA[mi] += 32;
        }
        float4 bp[2];
        #pragma unroll
        for (int p = 0; p < 2; p++) {
            bp[p] = *pB[p];
            pB[p] += (size_t)NTP * 32;
        }

        uint32_t bfr[4][2];
        bfr[0][0] = __float_as_uint(bp[0].x); bfr[0][1] = __float_as_uint(bp[0].y);
        bfr[1][0] = __float_as_uint(bp[0].z); bfr[1][1] = __float_as_uint(bp[0].w);
        bfr[2][0] = __float_as_uint(bp[1].x); bfr[2][1] = __float_as_uint(bp[1].y);
        bfr[3][0] = __float_as_uint(bp[1].z); bfr[3][1] = __float_as_uint(bp[1].w);

        #pragma unroll
        for (int mi = 0; mi < 4; mi++) {
            const uint32_t a0 = __float_as_uint(af[mi].x);
            const uint32_t a1 = __float_as_uint(af[mi].y);
            const uint32_t a2 = __float_as_uint(af[mi].z);
            const uint32_t a3 = __float_as_uint(af[mi].w);
            #pragma unroll
            for (int ni = 0; ni < 4; ni++)
                mma16n8k8(acc[mi][ni], a0, a1, a2, a3, bfr[ni][0], bfr[ni][1]);
        }
    }

    // epilogue: bias + store
    #pragma unroll
    for (int mi = 0; mi < 4; mi++) {
        const int row = o0 + wm * 64 + mi * 16 + gid;
        const float bias0 = g_bias[row];
        const float bias1 = g_bias[row + 8];
        float* y0 = y + ((size_t)b * COUT + row) * HW;
        #pragma unroll
        for (int ni = 0; ni < 4; ni++) {
            const int col = hw0 + (wn * 4 + ni) * 8 + tg * 2;
            if (col < HW) {
                float2 v0 = make_float2(acc[mi][ni][0] + bias0, acc[mi][ni][1] + bias0);
                float2 v1 = make_float2(acc[mi][ni][2] + bias1, acc[mi][ni][3] + bias1);
                *reinterpret_cast<float2*>(y0 + col) = v0;
                *reinterpret_cast<float2*>(y0 + (size_t)8 * HW + col) = v1;
            }
        }
    }
}

// ---------------- launch (serial) ----------------
extern "C" void kernel_launch(void* const* d_in, const int* in_sizes, int n_in,
                              void* d_out, int out_size) {
    const float* x    = (const float*)d_in[0];
    const float* fc_w = (const float*)d_in[1];
    const float* abn_g = (const float*)d_in[2];
    const float* abn_b = (const float*)d_in[3];
    const float* abn_m = (const float*)d_in[4];
    const float* abn_v = (const float*)d_in[5];
    const float* ch_w = (const float*)d_in[6];
    const float* ch_b = (const float*)d_in[7];
    const float* fl_w = (const float*)d_in[8];
    const float* fl_b = (const float*)d_in[9];
    const float* kn_w = (const float*)d_in[10];
    const float* kn_b = (const float*)d_in[11];
    const float* weight = (const float*)d_in[12];
    const float* bn_g = (const float*)d_in[13];
    const float* bn_b = (const float*)d_in[14];
    const float* bn_m = (const float*)d_in[15];
    const float* bn_v = (const float*)d_in[16];
    float* y = (float*)d_out;

    static bool attr_set = false;
    if (!attr_set) {
        cudaFuncSetAttribute(prepack_kernel,
                             cudaFuncAttributeMaxDynamicSharedMemorySize, PREPACK_SMEM_BYTES);
        attr_set = true;
    }

    prepack_kernel<<<BATCH * NKT8, 256, PREPACK_SMEM_BYTES>>>(x);   // 2048 blocks

    attn_kernel<<<dim3(BATCH, 2), 256>>>(fc_w, abn_g, abn_b, abn_m, abn_v,
                                         ch_w, ch_b, fl_w, fl_b, kn_w, kn_b,
                                         bn_g, bn_b, bn_m, bn_v);

    weff_kernel<<<NMT * NKT8 * 32 * 4 / 256, 256>>>(weight);   // 1024 blocks

    dim3 grid(COUT / BM, (HW + BN - 1) / BN, BATCH);  // (4, 25, 32)
    gemm_mma_kernel<<<grid, 256>>>(y);
}

// round 13
// speedup vs baseline: 1.0778x; 1.0778x over previous
#include <cuda_runtime.h>
#include <math.h>
#include <cstdint>

#define EPSF 1e-5f

// Problem constants
#define BATCH 32
#define CIN   512
#define COUT  512
#define HW    3136   // 56*56
#define KNUM  4
#define ADIM  32

#define NMT  (COUT / 16)   // 32 m-tiles
#define NKT8 (CIN / 8)     // 64 k8-tiles
#define NTP  (HW / 16)     // 196 n-tile-pairs

// GEMM tiling
#define BM 128
#define BN 64
#define BKK 32
#define NIT (CIN / BKK)          // 16 mainloop iterations
#define STAGES 3
#define A_STAGE_FLOATS (8 * 4 * 32 * 4)    // 4096
#define B_STAGE_FLOATS (4 * 4 * 32 * 4)    // 2048
#define STAGE_FLOATS (A_STAGE_FLOATS + B_STAGE_FLOATS)   // 6144
#define GEMM_SMEM_BYTES (STAGES * STAGE_FLOATS * 4)      // 73728 B

// prepack smem: 8 rows x (3136 + 8 pad) floats
#define PRE_SROW 3144
#define PREPACK_SMEM_BYTES (8 * PRE_SROW * 4)   // 100608 B

// ---------------- device scratch ----------------
__device__ float g_pooled[BATCH * CIN];
__device__ float g_ch[BATCH * CIN];
__device__ float g_rowscale[BATCH * COUT];
__device__ float g_kn[BATCH * KNUM];
__device__ float g_bias[COUT];
__device__ float g_weff[BATCH * NMT * NKT8 * 32 * 4];
__device__ float g_xpack[(size_t)BATCH * NKT8 * NTP * 32 * 4];

// ================= helpers =================
__device__ __forceinline__ float cvt_tf32(float v) {
    uint32_t u;
    asm("cvt.rna.tf32.f32 %0, %1;" : "=r"(u) : "f"(v));
    return __uint_as_float(u);
}

__device__ __forceinline__ void cp16(float* smem_dst, const float* gsrc, bool pred) {
    uint32_t s;
    asm("{ .reg .u64 t; cvta.to.shared.u64 t, %1; cvt.u32.u64 %0, t; }"
        : "=r"(s) : "l"(smem_dst));
    int sz = pred ? 16 : 0;
    asm volatile("cp.async.cg.shared.global [%0], [%1], 16, %2;"
                 :: "r"(s), "l"(gsrc), "r"(sz) : "memory");
}
#define CP_COMMIT() asm volatile("cp.async.commit_group;" ::: "memory")
#define CP_WAIT(n)  asm volatile("cp.async.wait_group %0;" :: "n"(n) : "memory")

__device__ __forceinline__ void mma16n8k8(float (&d)[4], const uint32_t a0, const uint32_t a1,
                                          const uint32_t a2, const uint32_t a3,
                                          const uint32_t b0, const uint32_t b1) {
    asm volatile(
        "mma.sync.aligned.m16n8k8.row.col.f32.tf32.tf32.f32 "
        "{%0,%1,%2,%3}, {%4,%5,%6,%7}, {%8,%9}, {%0,%1,%2,%3};"
        : "+f"(d[0]), "+f"(d[1]), "+f"(d[2]), "+f"(d[3])
        : "r"(a0), "r"(a1), "r"(a2), "r"(a3), "r"(b0), "r"(b1));
}

__device__ __forceinline__ float warp_sum(float v) {
    #pragma unroll
    for (int off = 16; off > 0; off >>= 1)
        v += __shfl_xor_sync(0xffffffffu, v, off);
    return v;
}

// ---------------- Kernel A: prepack x -> tf32 B-fragments, single sync -----
__global__ __launch_bounds__(256)
void prepack_kernel(const float* __restrict__ x) {
    extern __shared__ float sx[];   // [8][PRE_SROW]

    const int bx  = blockIdx.x;
    const int b   = bx >> 6;
    const int kt8 = bx & 63;
    const int tid = threadIdx.x;
    const int lane = tid & 31;
    const int w    = tid >> 5;

    const float4* Xr = reinterpret_cast<const float4*>(
        x + ((size_t)b * CIN + kt8 * 8 + w) * HW);
    float4* Op = reinterpret_cast<float4*>(g_xpack) +
                 ((size_t)(b * NKT8 + kt8) * NTP) * 32;

    float psum = 0.f;
    float* srow = sx + w * PRE_SROW;
    for (int i = lane; i < HW / 4; i += 32) {
        float4 v = Xr[i];
        psum += v.x + v.y + v.z + v.w;
        *reinterpret_cast<float4*>(&srow[i * 4]) = v;
    }
    psum = warp_sum(psum);
    if (lane == 0) g_pooled[b * CIN + kt8 * 8 + w] = psum * (1.0f / HW);

    __syncthreads();

    const int tg  = lane & 3;
    const int gid = lane >> 2;
    const float* r0 = sx + tg * PRE_SROW;
    const float* r1 = sx + (tg + 4) * PRE_SROW;
    #pragma unroll 5
    for (int r = 0; r < (NTP * 32 + 255) / 256; r++) {
        const int f = tid + 256 * r;
        const int ntpl = f >> 5;
        if (ntpl < NTP) {
            const int col0 = ntpl * 16 + gid;
            float4 o;
            o.x = cvt_tf32(r0[col0]);
            o.y = cvt_tf32(r1[col0]);
            o.z = cvt_tf32(r0[col0 + 8]);
            o.w = cvt_tf32(r1[col0 + 8]);
            Op[(size_t)ntpl * 32 + lane] = o;
        }
    }
}

// ---------------- Kernel B: attention heads (grid 32x2) ----------
__global__ __launch_bounds__(256)
void attn_kernel(const float* __restrict__ fc_w,
                 const float* __restrict__ abn_g, const float* __restrict__ abn_b,
                 const float* __restrict__ abn_m, const float* __restrict__ abn_v,
                 const float* __restrict__ ch_w, const float* __restrict__ ch_b,
                 const float* __restrict__ fl_w, const float* __restrict__ fl_b,
                 const float* __restrict__ kn_w, const float* __restrict__ kn_b,
                 const float* __restrict__ bn_g, const float* __restrict__ bn_b,
                 const float* __restrict__ bn_m, const float* __restrict__ bn_v) {
    __shared__ float sp[CIN];
    __shared__ float sh[ADIM];
    __shared__ float slog[KNUM];

    const int b = blockIdx.x;
    const int half = blockIdx.y;
    const int tid = threadIdx.x;
    const int wid = tid >> 5;
    const int lane = tid & 31;

    #pragma unroll
    for (int i = 0; i < CIN / 256; i++)
        sp[tid + 256 * i] = g_pooled[b * CIN + tid + 256 * i];
    __syncthreads();

    #pragma unroll
    for (int i = 0; i < 4; i++) {
        const int a = wid + 8 * i;
        const float* fr = &fc_w[a * CIN];
        float s = 0.f;
        #pragma unroll
        for (int c = 0; c < CIN / 32; c++)
            s += sp[lane + 32 * c] * fr[lane + 32 * c];
        s = warp_sum(s);
        if (lane == 0) {
            float inv_a = abn_g[a] * rsqrtf(abn_v[a] + EPSF);
            s = (s - abn_m[a]) * inv_a + abn_b[a];
            sh[a] = fmaxf(s, 0.f);
        }
    }
    __syncthreads();

    const float hv = sh[lane];

    if (half == 0) {
        for (int i = 0; i < 64; i++) {
            const int c = wid * 64 + i;
            float s = warp_sum(hv * ch_w[c * ADIM + lane]);
            if (lane == 0)
                g_ch[b * CIN + c] = 1.0f / (1.0f + __expf(-(s + ch_b[c])));
        }
    } else {
        for (int i = 0; i < 64; i++) {
            const int o = wid * 64 + i;
            float s = warp_sum(hv * fl_w[o * ADIM + lane]);
            if (lane == 0) {
                float fl = 1.0f / (1.0f + __expf(-(s + fl_b[o])));
                g_rowscale[b * COUT + o] = fl * bn_g[o] * rsqrtf(bn_v[o] + EPSF);
            }
        }
        if (wid == 0) {
            #pragma unroll
            for (int kk = 0; kk < KNUM; kk++) {
                float s = warp_sum(hv * kn_w[kk * ADIM + lane]);
                if (lane == 0) slog[kk] = s + kn_b[kk];
            }
            __syncwarp();
            if (lane == 0) {
                float m = fmaxf(fmaxf(slog[0], slog[1]), fmaxf(slog[2], slog[3]));
                float e0 = __expf(slog[0] - m), e1 = __expf(slog[1] - m);
                float e2 = __expf(slog[2] - m), e3 = __expf(slog[3] - m);
                float d = 1.0f / (e0 + e1 + e2 + e3);
                g_kn[b * KNUM + 0] = e0 * d;
                g_kn[b * KNUM + 1] = e1 * d;
                g_kn[b * KNUM + 2] = e2 * d;
                g_kn[b * KNUM + 3] = e3 * d;
            }
        }
        if (b == 0) {
            #pragma unroll
            for (int i = 0; i < COUT / 256; i++) {
                int o = tid + 256 * i;
                float inv = bn_g[o] * rsqrtf(bn_v[o] + EPSF);
                g_bias[o] = bn_b[o] - bn_m[o] * inv;
            }
        }
    }
}

// ---------------- Kernel C: effective weight, 4-way batch-split ----------------
__global__ __launch_bounds__(256)
void weff_kernel(const float* __restrict__ weight) {
    const int gidx = blockIdx.x * 256 + threadIdx.x;
    const int lane = gidx & 31;
    const int kt8 = (gidx >> 5) & (NKT8 - 1);
    const int mt  = (gidx >> 11) & (NMT - 1);
    const int bq  = gidx >> 16;            // 0..3

    const int gid = lane >> 2;
    const int tg  = lane & 3;
    const int o  = mt * 16 + gid;
    const int k  = kt8 * 8 + tg;

    float w[4][4];
    #pragma unroll
    for (int j = 0; j < KNUM; j++) {
        const float* wj = weight + ((size_t)j * COUT) * CIN;
        w[j][0] = wj[(size_t)o * CIN + k];
        w[j][1] = wj[(size_t)(o + 8) * CIN + k];
        w[j][2] = wj[(size_t)o * CIN + k + 4];
        w[j][3] = wj[(size_t)(o + 8) * CIN + k + 4];
    }

    float4* out = reinterpret_cast<float4*>(g_weff);
    const int b0 = bq * 8;
    #pragma unroll
    for (int bb = 0; bb < 8; bb++) {
        const int b = b0 + bb;
        const float kn0 = g_kn[b * KNUM + 0], kn1 = g_kn[b * KNUM + 1];
        const float kn2 = g_kn[b * KNUM + 2], kn3 = g_kn[b * KNUM + 3];
        const float rs0 = g_rowscale[b * COUT + o];
        const float rs1 = g_rowscale[b * COUT + o + 8];
        const float ch0 = g_ch[b * CIN + k];
        const float ch1 = g_ch[b * CIN + k + 4];

        float4 v;
        v.x = cvt_tf32(rs0 * ch0 * (kn0 * w[0][0] + kn1 * w[1][0] + kn2 * w[2][0] + kn3 * w[3][0]));
        v.y = cvt_tf32(rs1 * ch0 * (kn0 * w[0][1] + kn1 * w[1][1] + kn2 * w[2][1] + kn3 * w[3][1]));
        v.z = cvt_tf32(rs0 * ch1 * (kn0 * w[0][2] + kn1 * w[1][2] + kn2 * w[2][2] + kn3 * w[3][2]));
        v.w = cvt_tf32(rs1 * ch1 * (kn0 * w[0][3] + kn1 * w[1][3] + kn2 * w[2][3] + kn3 * w[3][3]));
        out[((size_t)(b * NMT + mt) * NKT8 + kt8) * 32 + lane] = v;
    }
}

// ---------------- Kernel D: mma.sync tf32 GEMM, BN=64, 3 CTAs/SM ----
__global__ __launch_bounds__(256, 3)
void gemm_mma_kernel(float* __restrict__ y) {
    extern __shared__ float smem[];

    const int tid  = threadIdx.x;
    const int lane = tid & 31;
    const int wid  = tid >> 5;
    const int wm   = wid >> 2;       // 0..1
    const int wn   = wid & 3;        // 0..3
    const int gid  = lane >> 2;
    const int tg   = lane & 3;

    const int mt0 = blockIdx.x * (BM / 16);   // 8 m-tiles per CTA
    const int o0  = blockIdx.x * BM;
    const int hw0 = blockIdx.y * BN;
    const int ntp0 = blockIdx.y * (BN / 16);  // 4 ntp per CTA (exact: 49*4=196)
    const int b   = blockIdx.z;

    // A staging: 1024 f4/stage; f = tid + 256r -> mt=f>>7, kt8l=(f>>5)&3, ln=f&31
    const float4* Wg4 = reinterpret_cast<const float4*>(g_weff);
    size_t a_g[4];
    #pragma unroll
    for (int r = 0; r < 4; r++) {
        const int f = tid + 256 * r;
        const int mt = f >> 7, kt8l = (f >> 5) & 3, ln = f & 31;
        a_g[r] = ((size_t)(b * NMT + mt0 + mt) * NKT8 + kt8l) * 32 + ln;
    }
    // B staging: 512 f4/stage; f = tid + 256r (r=0,1) -> kt8l=f>>7, ntp=(f>>5)&3, ln=f&31
    const float4* Xp4 = reinterpret_cast<const float4*>(g_xpack);
    size_t b_g[2];
    #pragma unroll
    for (int r = 0; r < 2; r++) {
        const int f = tid + 256 * r;
        const int kt8l = f >> 7, ntp = (f >> 5) & 3, ln = f & 31;
        b_g[r] = ((size_t)(b * NKT8 + kt8l) * NTP + ntp0 + ntp) * 32 + ln;
    }

    float acc[4][2][4];
    #pragma unroll
    for (int mi = 0; mi < 4; mi++)
        #pragma unroll
        for (int ni = 0; ni < 2; ni++)
            #pragma unroll
            for (int r = 0; r < 4; r++) acc[mi][ni][r] = 0.f;

    #pragma unroll
    for (int s = 0; s < STAGES - 1; s++) {
        float* As = smem + s * STAGE_FLOATS;
        float* Bs = As + A_STAGE_FLOATS;
        #pragma unroll
        for (int r = 0; r < 4; r++)
            cp16(&As[(tid + 256 * r) * 4], (const float*)(Wg4 + a_g[r] + (size_t)s * 128), true);
        #pragma unroll
        for (int r = 0; r < 2; r++)
            cp16(&Bs[(tid + 256 * r) * 4], (const float*)(Xp4 + b_g[r] + (size_t)s * 4 * NTP * 32), true);
        CP_COMMIT();
    }

    int cur = 0;
    for (int kc = 0; kc < NIT; kc++) {
        if (kc + 2 < NIT) { CP_WAIT(1); } else { CP_WAIT(0); }
        __syncthreads();

        if (kc + 2 < NIT) {
            int s = cur + 2; if (s >= STAGES) s -= STAGES;
            float* As = smem + s * STAGE_FLOATS;
            float* Bs = As + A_STAGE_FLOATS;
            #pragma unroll
            for (int r = 0; r < 4; r++)
                cp16(&As[(tid + 256 * r) * 4], (const float*)(Wg4 + a_g[r] + (size_t)(kc + 2) * 128), true);
            #pragma unroll
            for (int r = 0; r < 2; r++)
                cp16(&Bs[(tid + 256 * r) * 4], (const float*)(Xp4 + b_g[r] + (size_t)(kc + 2) * 4 * NTP * 32), true);
            CP_COMMIT();
        }

        const float* As = smem + cur * STAGE_FLOATS;
        const float4* Af = reinterpret_cast<const float4*>(As);
        const float4* Bf4 = reinterpret_cast<const float4*>(As + A_STAGE_FLOATS);

        #pragma unroll
        for (int kt = 0; kt < 4; kt++) {
            float4 af[4];
            #pragma unroll
            for (int mi = 0; mi < 4; mi++)
                af[mi] = Af[((wm * 4 + mi) * 4 + kt) * 32 + lane];
            // one ntp per warp: float4 = (b0,b1) nt-even, (b0,b1) nt-odd
            float4 bp = Bf4[(kt * 4 + wn) * 32 + lane];
            uint32_t bfr[2][2];
            bfr[0][0] = __float_as_uint(bp.x); bfr[0][1] = __float_as_uint(bp.y);
            bfr[1][0] = __float_as_uint(bp.z); bfr[1][1] = __float_as_uint(bp.w);
            #pragma unroll
            for (int mi = 0; mi < 4; mi++) {
                const uint32_t a0 = __float_as_uint(af[mi].x);
                const uint32_t a1 = __float_as_uint(af[mi].y);
                const uint32_t a2 = __float_as_uint(af[mi].z);
                const uint32_t a3 = __float_as_uint(af[mi].w);
                #pragma unroll
                for (int ni = 0; ni < 2; ni++)
                    mma16n8k8(acc[mi][ni], a0, a1, a2, a3, bfr[ni][0], bfr[ni][1]);
            }
        }
        cur++; if (cur == STAGES) cur = 0;
    }

    // epilogue: bias + store (col = hw0 + wn*16 + ni*8 + tg*2; always in bounds)
    #pragma unroll
    for (int mi = 0; mi < 4; mi++) {
        const int row = o0 + wm * 64 + mi * 16 + gid;
        const float bias0 = g_bias[row];
        const float bias1 = g_bias[row + 8];
        float* y0 = y + ((size_t)b * COUT + row) * HW;
        #pragma unroll
        for (int ni = 0; ni < 2; ni++) {
            const int col = hw0 + wn * 16 + ni * 8 + tg * 2;
            float2 v0 = make_float2(acc[mi][ni][0] + bias0, acc[mi][ni][1] + bias0);
            float2 v1 = make_float2(acc[mi][ni][2] + bias1, acc[mi][ni][3] + bias1);
            *reinterpret_cast<float2*>(y0 + col) = v0;
            *reinterpret_cast<float2*>(y0 + (size_t)8 * HW + col) = v1;
        }
    }
}

// ---------------- launch (serial) ----------------
extern "C" void kernel_launch(void* const* d_in, const int* in_sizes, int n_in,
                              void* d_out, int out_size) {
    const float* x    = (const float*)d_in[0];
    const float* fc_w = (const float*)d_in[1];
    const float* abn_g = (const float*)d_in[2];
    const float* abn_b = (const float*)d_in[3];
    const float* abn_m = (const float*)d_in[4];
    const float* abn_v = (const float*)d_in[5];
    const float* ch_w = (const float*)d_in[6];
    const float* ch_b = (const float*)d_in[7];
    const float* fl_w = (const float*)d_in[8];
    const float* fl_b = (const float*)d_in[9];
    const float* kn_w = (const float*)d_in[10];
    const float* kn_b = (const float*)d_in[11];
    const float* weight = (const float*)d_in[12];
    const float* bn_g = (const float*)d_in[13];
    const float* bn_b = (const float*)d_in[14];
    const float* bn_m = (const float*)d_in[15];
    const float* bn_v = (const float*)d_in[16];
    float* y = (float*)d_out;

    static bool attr_set = false;
    if (!attr_set) {
        cudaFuncSetAttribute(gemm_mma_kernel,
                             cudaFuncAttributeMaxDynamicSharedMemorySize, GEMM_SMEM_BYTES);
        cudaFuncSetAttribute(prepack_kernel,
                             cudaFuncAttributeMaxDynamicSharedMemorySize, PREPACK_SMEM_BYTES);
        attr_set = true;
    }

    prepack_kernel<<<BATCH * NKT8, 256, PREPACK_SMEM_BYTES>>>(x);   // 2048 blocks

    attn_kernel<<<dim3(BATCH, 2), 256>>>(fc_w, abn_g, abn_b, abn_m, abn_v,
                                         ch_w, ch_b, fl_w, fl_b, kn_w, kn_b,
                                         bn_g, bn_b, bn_m, bn_v);

    weff_kernel<<<NMT * NKT8 * 32 * 4 / 256, 256>>>(weight);   // 1024 blocks

    dim3 grid(COUT / BM, HW / BN, BATCH);  // (4, 49, 32)
    gemm_mma_kernel<<<grid, 256, GEMM_SMEM_BYTES>>>(y);
}

// round 14
// speedup vs baseline: 1.2393x; 1.1499x over previous
#include <cuda_runtime.h>
#include <math.h>
#include <cstdint>

#define EPSF 1e-5f

// Problem constants
#define BATCH 32
#define CIN   512
#define COUT  512
#define HW    3136   // 56*56
#define KNUM  4
#define ADIM  32

#define NMT  (COUT / 16)   // 32 m-tiles
#define NKT8 (CIN / 8)     // 64 k8-tiles
#define NTP  (HW / 16)     // 196 n-tile-pairs

// GEMM tiling (R11 configuration — frozen)
#define BM 128
#define BN 128
#define BKK 32
#define NIT (CIN / BKK)          // 16 mainloop iterations
#define STAGES 3
#define A_STAGE_FLOATS (8 * 4 * 32 * 4)    // 4096
#define B_STAGE_FLOATS (4 * 8 * 32 * 4)    // 4096
#define STAGE_FLOATS (A_STAGE_FLOATS + B_STAGE_FLOATS)
#define GEMM_SMEM_BYTES (STAGES * STAGE_FLOATS * 4)   // 98304 B

// prepack smem: 8 rows x (3136 + 8 pad) floats
#define PRE_SROW 3144
#define PREPACK_SMEM_BYTES (8 * PRE_SROW * 4)   // 100608 B

// ---------------- device scratch ----------------
__device__ float g_pooled[BATCH * CIN];
__device__ float g_ch[BATCH * CIN];
__device__ float g_rowscale[BATCH * COUT];
__device__ float g_kn[BATCH * KNUM];
__device__ float g_bias[COUT];
__device__ float g_weff[BATCH * NMT * NKT8 * 32 * 4];
__device__ float g_xpack[(size_t)BATCH * NKT8 * NTP * 32 * 4];

// ================= helpers =================
__device__ __forceinline__ float cvt_tf32(float v) {
    uint32_t u;
    asm("cvt.rna.tf32.f32 %0, %1;" : "=r"(u) : "f"(v));
    return __uint_as_float(u);
}

__device__ __forceinline__ void cp16(float* smem_dst, const float* gsrc, bool pred) {
    uint32_t s;
    asm("{ .reg .u64 t; cvta.to.shared.u64 t, %1; cvt.u32.u64 %0, t; }"
        : "=r"(s) : "l"(smem_dst));
    int sz = pred ? 16 : 0;
    asm volatile("cp.async.cg.shared.global [%0], [%1], 16, %2;"
                 :: "r"(s), "l"(gsrc), "r"(sz) : "memory");
}
#define CP_COMMIT() asm volatile("cp.async.commit_group;" ::: "memory")
#define CP_WAIT(n)  asm volatile("cp.async.wait_group %0;" :: "n"(n) : "memory")

__device__ __forceinline__ void mma16n8k8(float (&d)[4], const uint32_t a0, const uint32_t a1,
                                          const uint32_t a2, const uint32_t a3,
                                          const uint32_t b0, const uint32_t b1) {
    asm volatile(
        "mma.sync.aligned.m16n8k8.row.col.f32.tf32.tf32.f32 "
        "{%0,%1,%2,%3}, {%4,%5,%6,%7}, {%8,%9}, {%0,%1,%2,%3};"
        : "+f"(d[0]), "+f"(d[1]), "+f"(d[2]), "+f"(d[3])
        : "r"(a0), "r"(a1), "r"(a2), "r"(a3), "r"(b0), "r"(b1));
}

__device__ __forceinline__ float warp_sum(float v) {
    #pragma unroll
    for (int off = 16; off > 0; off >>= 1)
        v += __shfl_xor_sync(0xffffffffu, v, off);
    return v;
}

// ---------------- Kernel A: prepack x -> tf32 B-fragments (cp.async load) ---
__global__ __launch_bounds__(256)
void prepack_kernel(const float* __restrict__ x) {
    extern __shared__ float sx[];   // [8][PRE_SROW]

    const int bx  = blockIdx.x;
    const int b   = bx >> 6;
    const int kt8 = bx & 63;
    const int tid = threadIdx.x;
    const int lane = tid & 31;
    const int w    = tid >> 5;

    const float* Xr = x + ((size_t)b * CIN + kt8 * 8 + w) * HW;
    float4* Op = reinterpret_cast<float4*>(g_xpack) +
                 ((size_t)(b * NKT8 + kt8) * NTP) * 32;

    float* srow = sx + w * PRE_SROW;

    // async load of full row: fire-and-forget, max MLP
    for (int i = lane; i < HW / 4; i += 32)
        cp16(&srow[i * 4], Xr + i * 4, true);
    CP_COMMIT();
    CP_WAIT(0);
    __syncthreads();

    // pool: warp-local sum of own row from smem
    float psum = 0.f;
    for (int i = lane; i < HW / 4; i += 32) {
        float4 v = *reinterpret_cast<const float4*>(&srow[i * 4]);
        psum += v.x + v.y + v.z + v.w;
    }
    psum = warp_sum(psum);
    if (lane == 0) g_pooled[b * CIN + kt8 * 8 + w] = psum * (1.0f / HW);

    // gather into B-fragment layout
    const int tg  = lane & 3;
    const int gid = lane >> 2;
    const float* r0 = sx + tg * PRE_SROW;
    const float* r1 = sx + (tg + 4) * PRE_SROW;
    #pragma unroll 5
    for (int r = 0; r < (NTP * 32 + 255) / 256; r++) {
        const int f = tid + 256 * r;
        const int ntpl = f >> 5;
        if (ntpl < NTP) {
            const int col0 = ntpl * 16 + gid;
            float4 o;
            o.x = cvt_tf32(r0[col0]);
            o.y = cvt_tf32(r1[col0]);
            o.z = cvt_tf32(r0[col0 + 8]);
            o.w = cvt_tf32(r1[col0 + 8]);
            Op[(size_t)ntpl * 32 + lane] = o;
        }
    }
}

// ---------------- Kernel B: attention heads (grid 32x2) ----------
__global__ __launch_bounds__(256)
void attn_kernel(const float* __restrict__ fc_w,
                 const float* __restrict__ abn_g, const float* __restrict__ abn_b,
                 const float* __restrict__ abn_m, const float* __restrict__ abn_v,
                 const float* __restrict__ ch_w, const float* __restrict__ ch_b,
                 const float* __restrict__ fl_w, const float* __restrict__ fl_b,
                 const float* __restrict__ kn_w, const float* __restrict__ kn_b,
                 const float* __restrict__ bn_g, const float* __restrict__ bn_b,
                 const float* __restrict__ bn_m, const float* __restrict__ bn_v) {
    __shared__ float sp[CIN];
    __shared__ float sh[ADIM];
    __shared__ float slog[KNUM];

    const int b = blockIdx.x;
    const int half = blockIdx.y;
    const int tid = threadIdx.x;
    const int wid = tid >> 5;
    const int lane = tid & 31;

    #pragma unroll
    for (int i = 0; i < CIN / 256; i++)
        sp[tid + 256 * i] = g_pooled[b * CIN + tid + 256 * i];
    __syncthreads();

    #pragma unroll
    for (int i = 0; i < 4; i++) {
        const int a = wid + 8 * i;
        const float* fr = &fc_w[a * CIN];
        float s = 0.f;
        #pragma unroll
        for (int c = 0; c < CIN / 32; c++)
            s += sp[lane + 32 * c] * fr[lane + 32 * c];
        s = warp_sum(s);
        if (lane == 0) {
            float inv_a = abn_g[a] * rsqrtf(abn_v[a] + EPSF);
            s = (s - abn_m[a]) * inv_a + abn_b[a];
            sh[a] = fmaxf(s, 0.f);
        }
    }
    __syncthreads();

    const float hv = sh[lane];

    if (half == 0) {
        for (int i = 0; i < 64; i++) {
            const int c = wid * 64 + i;
            float s = warp_sum(hv * ch_w[c * ADIM + lane]);
            if (lane == 0)
                g_ch[b * CIN + c] = 1.0f / (1.0f + __expf(-(s + ch_b[c])));
        }
    } else {
        for (int i = 0; i < 64; i++) {
            const int o = wid * 64 + i;
            float s = warp_sum(hv * fl_w[o * ADIM + lane]);
            if (lane == 0) {
                float fl = 1.0f / (1.0f + __expf(-(s + fl_b[o])));
                g_rowscale[b * COUT + o] = fl * bn_g[o] * rsqrtf(bn_v[o] + EPSF);
            }
        }
        if (wid == 0) {
            #pragma unroll
            for (int kk = 0; kk < KNUM; kk++) {
                float s = warp_sum(hv * kn_w[kk * ADIM + lane]);
                if (lane == 0) slog[kk] = s + kn_b[kk];
            }
            __syncwarp();
            if (lane == 0) {
                float m = fmaxf(fmaxf(slog[0], slog[1]), fmaxf(slog[2], slog[3]));
                float e0 = __expf(slog[0] - m), e1 = __expf(slog[1] - m);
                float e2 = __expf(slog[2] - m), e3 = __expf(slog[3] - m);
                float d = 1.0f / (e0 + e1 + e2 + e3);
                g_kn[b * KNUM + 0] = e0 * d;
                g_kn[b * KNUM + 1] = e1 * d;
                g_kn[b * KNUM + 2] = e2 * d;
                g_kn[b * KNUM + 3] = e3 * d;
            }
        }
        if (b == 0) {
            #pragma unroll
            for (int i = 0; i < COUT / 256; i++) {
                int o = tid + 256 * i;
                float inv = bn_g[o] * rsqrtf(bn_v[o] + EPSF);
                g_bias[o] = bn_b[o] - bn_m[o] * inv;
            }
        }
    }
}

// ---------------- Kernel C: effective weight, 4-way batch-split ----------------
__global__ __launch_bounds__(256)
void weff_kernel(const float* __restrict__ weight) {
    const int gidx = blockIdx.x * 256 + threadIdx.x;
    const int lane = gidx & 31;
    const int kt8 = (gidx >> 5) & (NKT8 - 1);
    const int mt  = (gidx >> 11) & (NMT - 1);
    const int bq  = gidx >> 16;            // 0..3

    const int gid = lane >> 2;
    const int tg  = lane & 3;
    const int o  = mt * 16 + gid;
    const int k  = kt8 * 8 + tg;

    float w[4][4];
    #pragma unroll
    for (int j = 0; j < KNUM; j++) {
        const float* wj = weight + ((size_t)j * COUT) * CIN;
        w[j][0] = wj[(size_t)o * CIN + k];
        w[j][1] = wj[(size_t)(o + 8) * CIN + k];
        w[j][2] = wj[(size_t)o * CIN + k + 4];
        w[j][3] = wj[(size_t)(o + 8) * CIN + k + 4];
    }

    float4* out = reinterpret_cast<float4*>(g_weff);
    const int b0 = bq * 8;
    #pragma unroll
    for (int bb = 0; bb < 8; bb++) {
        const int b = b0 + bb;
        const float kn0 = g_kn[b * KNUM + 0], kn1 = g_kn[b * KNUM + 1];
        const float kn2 = g_kn[b * KNUM + 2], kn3 = g_kn[b * KNUM + 3];
        const float rs0 = g_rowscale[b * COUT + o];
        const float rs1 = g_rowscale[b * COUT + o + 8];
        const float ch0 = g_ch[b * CIN + k];
        const float ch1 = g_ch[b * CIN + k + 4];

        float4 v;
        v.x = cvt_tf32(rs0 * ch0 * (kn0 * w[0][0] + kn1 * w[1][0] + kn2 * w[2][0] + kn3 * w[3][0]));
        v.y = cvt_tf32(rs1 * ch0 * (kn0 * w[0][1] + kn1 * w[1][1] + kn2 * w[2][1] + kn3 * w[3][1]));
        v.z = cvt_tf32(rs0 * ch1 * (kn0 * w[0][2] + kn1 * w[1][2] + kn2 * w[2][2] + kn3 * w[3][2]));
        v.w = cvt_tf32(rs1 * ch1 * (kn0 * w[0][3] + kn1 * w[1][3] + kn2 * w[2][3] + kn3 * w[3][3]));
        out[((size_t)(b * NMT + mt) * NKT8 + kt8) * 32 + lane] = v;
    }
}

// ---------------- Kernel D: mma.sync tf32 GEMM (R11 frozen config) ----
__global__ __launch_bounds__(256, 2)
void gemm_mma_kernel(float* __restrict__ y) {
    extern __shared__ float smem[];

    const int tid  = threadIdx.x;
    const int lane = tid & 31;
    const int wid  = tid >> 5;
    const int wm   = wid >> 2;
    const int wn   = wid & 3;
    const int gid  = lane >> 2;
    const int tg   = lane & 3;

    const int mt0 = blockIdx.x * (BM / 16);
    const int o0  = blockIdx.x * BM;
    const int hw0 = blockIdx.y * BN;
    const int ntp0 = blockIdx.y * (BN / 16);
    const int b   = blockIdx.z;

    const float4* Wg4 = reinterpret_cast<const float4*>(g_weff);
    size_t a_g[4];
    #pragma unroll
    for (int r = 0; r < 4; r++) {
        const int f = tid + 256 * r;
        const int mt = f >> 7, kt8l = (f >> 5) & 3, ln = f & 31;
        a_g[r] = ((size_t)(b * NMT + mt0 + mt) * NKT8 + kt8l) * 32 + ln;
    }
    const float4* Xp4 = reinterpret_cast<const float4*>(g_xpack);
    size_t b_g[4];
    bool b_pred[4];
    #pragma unroll
    for (int r = 0; r < 4; r++) {
        const int f = tid + 256 * r;
        const int kt8l = f >> 8, ntp = (f >> 5) & 7, ln = f & 31;
        b_g[r] = ((size_t)(b * NKT8 + kt8l) * NTP + ntp0 + ntp) * 32 + ln;
        b_pred[r] = (ntp0 + ntp) < NTP;
    }

    float acc[4][4][4];
    #pragma unroll
    for (int mi = 0; mi < 4; mi++)
        #pragma unroll
        for (int ni = 0; ni < 4; ni++)
            #pragma unroll
            for (int r = 0; r < 4; r++) acc[mi][ni][r] = 0.f;

    #pragma unroll
    for (int s = 0; s < STAGES - 1; s++) {
        float* As = smem + s * STAGE_FLOATS;
        float* Bs = As + A_STAGE_FLOATS;
        #pragma unroll
        for (int r = 0; r < 4; r++) {
            const int f = tid + 256 * r;
            cp16(&As[f * 4], (const float*)(Wg4 + a_g[r] + (size_t)s * 128), true);
            cp16(&Bs[f * 4], (const float*)(Xp4 + b_g[r] + (size_t)s * 4 * NTP * 32), b_pred[r]);
        }
        CP_COMMIT();
    }

    int cur = 0;
    for (int kc = 0; kc < NIT; kc++) {
        if (kc + 2 < NIT) { CP_WAIT(1); } else { CP_WAIT(0); }
        __syncthreads();

        if (kc + 2 < NIT) {
            int s = cur + 2; if (s >= STAGES) s -= STAGES;
            float* As = smem + s * STAGE_FLOATS;
            float* Bs = As + A_STAGE_FLOATS;
            #pragma unroll
            for (int r = 0; r < 4; r++) {
                const int f = tid + 256 * r;
                cp16(&As[f * 4], (const float*)(Wg4 + a_g[r] + (size_t)(kc + 2) * 128), true);
                cp16(&Bs[f * 4], (const float*)(Xp4 + b_g[r] + (size_t)(kc + 2) * 4 * NTP * 32), b_pred[r]);
            }
            CP_COMMIT();
        }

        const float* As = smem + cur * STAGE_FLOATS;
        const float4* Af = reinterpret_cast<const float4*>(As);
        const float4* Bf4 = reinterpret_cast<const float4*>(As + A_STAGE_FLOATS);

        #pragma unroll
        for (int kt = 0; kt < 4; kt++) {
            float4 af[4];
            #pragma unroll
            for (int mi = 0; mi < 4; mi++)
                af[mi] = Af[((wm * 4 + mi) * 4 + kt) * 32 + lane];
            float4 bp[2];
            #pragma unroll
            for (int p = 0; p < 2; p++)
                bp[p] = Bf4[((kt * 8) + wn * 2 + p) * 32 + lane];
            uint32_t bfr[4][2];
            bfr[0][0] = __float_as_uint(bp[0].x); bfr[0][1] = __float_as_uint(bp[0].y);
            bfr[1][0] = __float_as_uint(bp[0].z); bfr[1][1] = __float_as_uint(bp[0].w);
            bfr[2][0] = __float_as_uint(bp[1].x); bfr[2][1] = __float_as_uint(bp[1].y);
            bfr[3][0] = __float_as_uint(bp[1].z); bfr[3][1] = __float_as_uint(bp[1].w);
            #pragma unroll
            for (int mi = 0; mi < 4; mi++) {
                const uint32_t a0 = __float_as_uint(af[mi].x);
                const uint32_t a1 = __float_as_uint(af[mi].y);
                const uint32_t a2 = __float_as_uint(af[mi].z);
                const uint32_t a3 = __float_as_uint(af[mi].w);
                #pragma unroll
                for (int ni = 0; ni < 4; ni++)
                    mma16n8k8(acc[mi][ni], a0, a1, a2, a3, bfr[ni][0], bfr[ni][1]);
            }
        }
        cur++; if (cur == STAGES) cur = 0;
    }

    #pragma unroll
    for (int mi = 0; mi < 4; mi++) {
        const int row = o0 + wm * 64 + mi * 16 + gid;
        const float bias0 = g_bias[row];
        const float bias1 = g_bias[row + 8];
        float* y0 = y + ((size_t)b * COUT + row) * HW;
        #pragma unroll
        for (int ni = 0; ni < 4; ni++) {
            const int col = hw0 + (wn * 4 + ni) * 8 + tg * 2;
            if (col < HW) {
                float2 v0 = make_float2(acc[mi][ni][0] + bias0, acc[mi][ni][1] + bias0);
                float2 v1 = make_float2(acc[mi][ni][2] + bias1, acc[mi][ni][3] + bias1);
                *reinterpret_cast<float2*>(y0 + col) = v0;
                *reinterpret_cast<float2*>(y0 + (size_t)8 * HW + col) = v1;
            }
        }
    }
}

// ---------------- launch (serial) ----------------
extern "C" void kernel_launch(void* const* d_in, const int* in_sizes, int n_in,
                              void* d_out, int out_size) {
    const float* x    = (const float*)d_in[0];
    const float* fc_w = (const float*)d_in[1];
    const float* abn_g = (const float*)d_in[2];
    const float* abn_b = (const float*)d_in[3];
    const float* abn_m = (const float*)d_in[4];
    const float* abn_v = (const float*)d_in[5];
    const float* ch_w = (const float*)d_in[6];
    const float* ch_b = (const float*)d_in[7];
    const float* fl_w = (const float*)d_in[8];
    const float* fl_b = (const float*)d_in[9];
    const float* kn_w = (const float*)d_in[10];
    const float* kn_b = (const float*)d_in[11];
    const float* weight = (const float*)d_in[12];
    const float* bn_g = (const float*)d_in[13];
    const float* bn_b = (const float*)d_in[14];
    const float* bn_m = (const float*)d_in[15];
    const float* bn_v = (const float*)d_in[16];
    float* y = (float*)d_out;

    static bool attr_set = false;
    if (!attr_set) {
        cudaFuncSetAttribute(gemm_mma_kernel,
                             cudaFuncAttributeMaxDynamicSharedMemorySize, GEMM_SMEM_BYTES);
        cudaFuncSetAttribute(prepack_kernel,
                             cudaFuncAttributeMaxDynamicSharedMemorySize, PREPACK_SMEM_BYTES);
        attr_set = true;
    }

    prepack_kernel<<<BATCH * NKT8, 256, PREPACK_SMEM_BYTES>>>(x);   // 2048 blocks

    attn_kernel<<<dim3(BATCH, 2), 256>>>(fc_w, abn_g, abn_b, abn_m, abn_v,
                                         ch_w, ch_b, fl_w, fl_b, kn_w, kn_b,
                                         bn_g, bn_b, bn_m, bn_v);

    weff_kernel<<<NMT * NKT8 * 32 * 4 / 256, 256>>>(weight);   // 1024 blocks

    dim3 grid(COUT / BM, (HW + BN - 1) / BN, BATCH);  // (4, 25, 32)
    gemm_mma_kernel<<<grid, 256, GEMM_SMEM_BYTES>>>(y);
}